// round 2
// baseline (speedup 1.0000x reference)
#include <cuda_runtime.h>
#include <math.h>

#define TSRC 64
#define BB   64
#define EE   512
#define HH   1024
#define H4   4096
#define VV   32000
#define TD   63   // decoder steps

// ---------------- scratch layout (floats) ----------------
constexpr size_t SZ_X    = (size_t)TSRC*BB*EE;       // src embeddings
constexpr size_t SZ_Y    = (size_t)TD*BB*EE;         // dst embeddings
constexpr size_t SZ_XF   = (size_t)TSRC*BB*H4;       // x@Wihf^T + bias
constexpr size_t SZ_YW   = (size_t)TD*BB*H4;         // y@Wihd[:, :512]^T + bias
constexpr size_t SZ_OUTH = (size_t)TSRC*BB*HH;
constexpr size_t SZ_ENCH = (size_t)BB*TSRC*2*HH;
constexpr size_t SZ_ENCP = (size_t)BB*TSRC*HH;
constexpr size_t SZ_OUTS = (size_t)TD*BB*HH;
constexpr size_t SZ_BH   = (size_t)BB*HH;
constexpr size_t SZ_CAT2 = (size_t)BB*2*HH;
constexpr size_t SZ_CAT3 = (size_t)BB*3*HH;
constexpr size_t SZ_PART = (size_t)12*BB*H4;
constexpr size_t SZ_BS   = (size_t)3*H4;
constexpr size_t SZ_ROWS = (size_t)4096;             // padded TD*BB
constexpr size_t SZ_PM   = (size_t)250*4096;

constexpr size_t OFF_X    = 0;
constexpr size_t OFF_Y    = OFF_X    + SZ_X;
constexpr size_t OFF_XF   = OFF_Y    + SZ_Y;
constexpr size_t OFF_XB   = OFF_XF   + SZ_XF;
constexpr size_t OFF_YW   = OFF_XB   + SZ_XF;
constexpr size_t OFF_OUTF = OFF_YW   + SZ_YW;
constexpr size_t OFF_OUTB = OFF_OUTF + SZ_OUTH;
constexpr size_t OFF_ENCH = OFF_OUTB + SZ_OUTH;
constexpr size_t OFF_ENCP = OFF_ENCH + SZ_ENCH;
constexpr size_t OFF_OUTS = OFF_ENCP + SZ_ENCP;
constexpr size_t OFF_H    = OFF_OUTS + SZ_OUTS;
constexpr size_t OFF_C    = OFF_H    + SZ_BH;
constexpr size_t OFF_H0   = OFF_C    + SZ_BH;
constexpr size_t OFF_C0   = OFF_H0   + SZ_BH;
constexpr size_t OFF_O0   = OFF_C0   + SZ_BH;
constexpr size_t OFF_HCAT = OFF_O0   + SZ_BH;
constexpr size_t OFF_CCAT = OFF_HCAT + SZ_CAT2;
constexpr size_t OFF_ATT  = OFF_CCAT + SZ_CAT2;
constexpr size_t OFF_PART = OFF_ATT  + SZ_CAT3;
constexpr size_t OFF_BS   = OFF_PART + SZ_PART;
constexpr size_t OFF_GOLD = OFF_BS   + SZ_BS;
constexpr size_t OFF_LSE  = OFF_GOLD + SZ_ROWS;
constexpr size_t OFF_PMAX = OFF_LSE  + SZ_ROWS;
constexpr size_t OFF_PSUM = OFF_PMAX + SZ_PM;
constexpr size_t TOTAL    = OFF_PSUM + SZ_PM;

__device__ float g_buf[TOTAL];

__device__ __forceinline__ float sigm(float x) { return 1.0f / (1.0f + expf(-x)); }

// ---------------- utility kernels ----------------
__global__ void zero_k(float* p, int n) {
    int i = blockIdx.x * blockDim.x + threadIdx.x;
    if (i < n) p[i] = 0.f;
}

__global__ void bias3_k(float* bs,
                        const float* __restrict__ a1, const float* __restrict__ a2,
                        const float* __restrict__ b1, const float* __restrict__ b2,
                        const float* __restrict__ c1, const float* __restrict__ c2) {
    int j = blockIdx.x * 256 + threadIdx.x;
    if (j < H4) {
        bs[j]        = a1[j] + a2[j];
        bs[H4 + j]   = b1[j] + b2[j];
        bs[2*H4 + j] = c1[j] + c2[j];
    }
}

// one block per row; 128 threads * float4 = 512 floats
__global__ void gather_k(float* __restrict__ out, const float* __restrict__ emb,
                         const int* __restrict__ idx) {
    int row = blockIdx.x;
    int id  = idx[row];
    const float4* s = (const float4*)(emb + (size_t)id * EE);
    float4* d = (float4*)(out + (size_t)row * EE);
    d[threadIdx.x] = s[threadIdx.x];
}

__global__ void copycat_k(float* __restrict__ dst, const float* __restrict__ src, int off) {
    int idx = blockIdx.x * 256 + threadIdx.x;   // 65536
    int b = idx >> 10, j = idx & 1023;
    dst[(size_t)b * 2048 + off + j] = src[idx];
}

__global__ void ench_k(float* __restrict__ ench, const float* __restrict__ outf,
                       const float* __restrict__ outb) {
    int idx = blockIdx.x * 256 + threadIdx.x;   // TSRC*BB*HH
    int t = idx >> 16;
    int r = idx & 65535;
    int b = r >> 10, j = r & 1023;
    size_t dst = (size_t)b * (TSRC*2*HH) + (size_t)t * 2*HH + j;
    ench[dst]      = outf[idx];
    ench[dst + HH] = outb[idx];
}

__global__ void sumsl_k(float* __restrict__ dst, const float* __restrict__ part, int ns) {
    int idx = blockIdx.x * 256 + threadIdx.x;   // 65536
    float s = 0.f;
    for (int q = 0; q < ns; q++) s += part[(size_t)q * 65536 + idx];
    dst[idx] = s;
}

__global__ void tanhsum_k(float* __restrict__ dst, const float* __restrict__ part, int ns) {
    int idx = blockIdx.x * 256 + threadIdx.x;   // 65536
    float s = 0.f;
    for (int q = 0; q < ns; q++) s += part[(size_t)q * 65536 + idx];
    dst[idx] = tanhf(s);
}

// ---------------- big GEMM: 128x128 tile, 8x8 micro ----------------
// C[m,n] = sum_k A[m*lda+k] * B[n*ldb+k] (+ bias[n]).  N%128==0, K%16==0.
__global__ __launch_bounds__(256)
void sgemm128(const float* __restrict__ A, int lda,
              const float* __restrict__ B, int ldb,
              float* __restrict__ C, int ldc,
              int M, int K, const float* __restrict__ bias) {
    __shared__ float As[16][132];
    __shared__ float Bs[16][132];
    const int bm = blockIdx.y * 128;
    const int bn = blockIdx.x * 128;
    const int tid = threadIdx.x;
    const int lr = tid >> 2;
    const int lc = (tid & 3) << 2;
    const int ty = tid >> 4;
    const int tx = tid & 15;
    float acc[8][8];
    #pragma unroll
    for (int i = 0; i < 8; i++)
        #pragma unroll
        for (int j = 0; j < 8; j++) acc[i][j] = 0.f;

    for (int kt = 0; kt < K; kt += 16) {
        #pragma unroll
        for (int h = 0; h < 2; h++) {
            int r = lr + h * 64;
            int gr = bm + r;
            float4 v = make_float4(0.f, 0.f, 0.f, 0.f);
            if (gr < M) v = *(const float4*)(A + (size_t)gr * lda + kt + lc);
            As[lc+0][r] = v.x; As[lc+1][r] = v.y; As[lc+2][r] = v.z; As[lc+3][r] = v.w;
            float4 w = *(const float4*)(B + (size_t)(bn + r) * ldb + kt + lc);
            Bs[lc+0][r] = w.x; Bs[lc+1][r] = w.y; Bs[lc+2][r] = w.z; Bs[lc+3][r] = w.w;
        }
        __syncthreads();
        #pragma unroll
        for (int k = 0; k < 16; k++) {
            float4 a0 = *(const float4*)&As[k][ty*8];
            float4 a1 = *(const float4*)&As[k][ty*8+4];
            float4 b0 = *(const float4*)&Bs[k][tx*8];
            float4 b1 = *(const float4*)&Bs[k][tx*8+4];
            float av[8] = {a0.x,a0.y,a0.z,a0.w,a1.x,a1.y,a1.z,a1.w};
            float bv[8] = {b0.x,b0.y,b0.z,b0.w,b1.x,b1.y,b1.z,b1.w};
            #pragma unroll
            for (int i = 0; i < 8; i++)
                #pragma unroll
                for (int j = 0; j < 8; j++) acc[i][j] += av[i] * bv[j];
        }
        __syncthreads();
    }
    #pragma unroll
    for (int i = 0; i < 8; i++) {
        int gm = bm + ty * 8 + i;
        if (gm >= M) continue;
        #pragma unroll
        for (int j = 0; j < 8; j++) {
            int gn = bn + tx * 8 + j;
            float v = acc[i][j];
            if (bias) v += bias[gn];
            C[(size_t)gm * ldc + gn] = v;
        }
    }
}

// ---------------- small-M (M=64) partial GEMM, K-split ----------------
// out_slot[b, bn+n] = sum_{k in split} A[b*lda+k] * W[(bn+n)*ldw+k]
// grid: (Ntot/64, splits), 256 threads. out pointer for split s = out + s*slotStride.
__global__ __launch_bounds__(256)
void pgemm(const float* __restrict__ A, int lda,
           const float* __restrict__ W, int ldw,
           float* __restrict__ out, int Ntot, int Kper, size_t slotStride) {
    __shared__ float As[16][68];
    __shared__ float Ws[16][68];
    const int bn = blockIdx.x * 64;
    const int s  = blockIdx.y;
    const int k0 = s * Kper;
    out += (size_t)s * slotStride;
    const int tid = threadIdx.x;
    const int lr = tid >> 2;
    const int lc = (tid & 3) << 2;
    const int ty = tid >> 4;
    const int tx = tid & 15;
    float acc[4][4];
    #pragma unroll
    for (int i = 0; i < 4; i++)
        #pragma unroll
        for (int j = 0; j < 4; j++) acc[i][j] = 0.f;

    for (int kt = k0; kt < k0 + Kper; kt += 16) {
        float4 v = *(const float4*)(A + (size_t)lr * lda + kt + lc);
        As[lc+0][lr] = v.x; As[lc+1][lr] = v.y; As[lc+2][lr] = v.z; As[lc+3][lr] = v.w;
        float4 w = *(const float4*)(W + (size_t)(bn + lr) * ldw + kt + lc);
        Ws[lc+0][lr] = w.x; Ws[lc+1][lr] = w.y; Ws[lc+2][lr] = w.z; Ws[lc+3][lr] = w.w;
        __syncthreads();
        #pragma unroll
        for (int k = 0; k < 16; k++) {
            float4 a = *(const float4*)&As[k][ty*4];
            float4 b = *(const float4*)&Ws[k][tx*4];
            float av[4] = {a.x,a.y,a.z,a.w};
            float bv[4] = {b.x,b.y,b.z,b.w};
            #pragma unroll
            for (int i = 0; i < 4; i++)
                #pragma unroll
                for (int j = 0; j < 4; j++) acc[i][j] += av[i] * bv[j];
        }
        __syncthreads();
    }
    #pragma unroll
    for (int i = 0; i < 4; i++) {
        int b = ty * 4 + i;
        #pragma unroll
        for (int j = 0; j < 4; j++)
            out[(size_t)b * Ntot + bn + tx * 4 + j] = acc[i][j];
    }
}

// ---------------- LSTM cell (gates = X + sum parts) ----------------
__global__ void cell_k(const float* __restrict__ X, const float* __restrict__ part,
                       int ns, float* __restrict__ h, float* __restrict__ c,
                       float* __restrict__ outp, const int* __restrict__ lens, int t) {
    int idx = blockIdx.x * 256 + threadIdx.x;   // B*HH = 65536
    int b = idx >> 10, j = idx & 1023;
    size_t base = (size_t)b * H4 + j;
    float gi = X[base], gf = X[base + HH], gg = X[base + 2*HH], go = X[base + 3*HH];
    for (int q = 0; q < ns; q++) {
        const float* p = part + (size_t)q * (BB*H4);
        gi += p[base]; gf += p[base + HH]; gg += p[base + 2*HH]; go += p[base + 3*HH];
    }
    float cold = c[idx];
    float c2 = sigm(gf) * cold + sigm(gi) * tanhf(gg);
    float h2 = sigm(go) * tanhf(c2);
    bool m = lens ? (t < lens[b]) : true;
    h[idx] = m ? h2 : h[idx];
    c[idx] = m ? c2 : cold;
    if (outp) outp[idx] = m ? h2 : 0.f;
}

// ---------------- attention (one block per batch) ----------------
__global__ __launch_bounds__(256)
void att_k(const float* __restrict__ encp, const float* __restrict__ ench,
           const float* __restrict__ h, const int* __restrict__ lens,
           float* __restrict__ cat) {
    __shared__ float e[64];
    __shared__ float alpha[64];
    const int b = blockIdx.x;
    const int tid = threadIdx.x;
    const int w = tid >> 5, l = tid & 31;
    const int len = lens[b];
    for (int t = w; t < 64; t += 8) {
        const float* ep = encp + ((size_t)b * 64 + t) * HH;
        const float* hp = h + (size_t)b * HH;
        float s = 0.f;
        for (int k = l; k < HH; k += 32) s += ep[k] * hp[k];
        #pragma unroll
        for (int m = 16; m > 0; m >>= 1) s += __shfl_xor_sync(0xffffffff, s, m);
        if (l == 0) e[t] = s;
    }
    __syncthreads();
    if (tid == 0) {
        float mx = -1e30f;
        for (int t = 0; t < len; t++) mx = fmaxf(mx, e[t]);
        float sm = 0.f;
        for (int t = 0; t < len; t++) sm += expf(e[t] - mx);
        float inv = 1.f / sm;
        for (int t = 0; t < 64; t++) alpha[t] = (t < len) ? expf(e[t] - mx) * inv : 0.f;
    }
    __syncthreads();
    const float* eh = ench + (size_t)b * (64 * 2048);
    for (int d = tid; d < 2048; d += 256) {
        float s = 0.f;
        for (int t = 0; t < len; t++) s += alpha[t] * eh[(size_t)t * 2048 + d];
        cat[(size_t)b * 3072 + d] = s;
    }
    for (int d = tid; d < 1024; d += 256)
        cat[(size_t)b * 3072 + 2048 + d] = h[(size_t)b * HH + d];
}

// ---------------- vocab GEMM with fused per-chunk (max, sumexp) ----------------
// grid (250, 32): blockIdx.x = 128-col chunk, blockIdx.y = 128-row tile.
__global__ __launch_bounds__(256)
void vgemm(const float* __restrict__ A, const float* __restrict__ B,
           float* __restrict__ pmax, float* __restrict__ psum, int M) {
    __shared__ float As[16][132];
    __shared__ float Bs[16][132];
    const int bm = blockIdx.y * 128;
    const int bn = blockIdx.x * 128;
    const int chunk = blockIdx.x;
    const int tid = threadIdx.x;
    const int lr = tid >> 2;
    const int lc = (tid & 3) << 2;
    const int ty = tid >> 4;
    const int tx = tid & 15;
    float acc[8][8];
    #pragma unroll
    for (int i = 0; i < 8; i++)
        #pragma unroll
        for (int j = 0; j < 8; j++) acc[i][j] = 0.f;

    for (int kt = 0; kt < HH; kt += 16) {
        #pragma unroll
        for (int h = 0; h < 2; h++) {
            int r = lr + h * 64;
            int gr = bm + r;
            float4 v = make_float4(0.f, 0.f, 0.f, 0.f);
            if (gr < M) v = *(const float4*)(A + (size_t)gr * HH + kt + lc);
            As[lc+0][r] = v.x; As[lc+1][r] = v.y; As[lc+2][r] = v.z; As[lc+3][r] = v.w;
            float4 w = *(const float4*)(B + (size_t)(bn + r) * HH + kt + lc);
            Bs[lc+0][r] = w.x; Bs[lc+1][r] = w.y; Bs[lc+2][r] = w.z; Bs[lc+3][r] = w.w;
        }
        __syncthreads();
        #pragma unroll
        for (int k = 0; k < 16; k++) {
            float4 a0 = *(const float4*)&As[k][ty*8];
            float4 a1 = *(const float4*)&As[k][ty*8+4];
            float4 b0 = *(const float4*)&Bs[k][tx*8];
            float4 b1 = *(const float4*)&Bs[k][tx*8+4];
            float av[8] = {a0.x,a0.y,a0.z,a0.w,a1.x,a1.y,a1.z,a1.w};
            float bv[8] = {b0.x,b0.y,b0.z,b0.w,b1.x,b1.y,b1.z,b1.w};
            #pragma unroll
            for (int i = 0; i < 8; i++)
                #pragma unroll
                for (int j = 0; j < 8; j++) acc[i][j] += av[i] * bv[j];
        }
        __syncthreads();
    }
    // per-row (max, sumexp) over this 128-col chunk
    #pragma unroll
    for (int i = 0; i < 8; i++) {
        float Mx = acc[i][0];
        #pragma unroll
        for (int j = 1; j < 8; j++) Mx = fmaxf(Mx, acc[i][j]);
        float S = 0.f;
        #pragma unroll
        for (int j = 0; j < 8; j++) S += expf(acc[i][j] - Mx);
        // combine across the 16 tx lanes (half-warp: lane = (ty&1)*16 + tx)
        #pragma unroll
        for (int m = 1; m < 16; m <<= 1) {
            float M2 = __shfl_xor_sync(0xffffffff, Mx, m);
            float S2 = __shfl_xor_sync(0xffffffff, S, m);
            float Mn = fmaxf(Mx, M2);
            S = S * expf(Mx - Mn) + S2 * expf(M2 - Mn);
            Mx = Mn;
        }
        if (tx == 0) {
            int row = bm + ty * 8 + i;
            if (row < M) {
                pmax[(size_t)chunk * 4096 + row] = Mx;
                psum[(size_t)chunk * 4096 + row] = S;
            }
        }
    }
}

// lse[row] = combined logsumexp over 250 chunks. one warp per row.
__global__ void lse_k(const float* __restrict__ pmax, const float* __restrict__ psum,
                      float* __restrict__ lse, int M) {
    int row = blockIdx.x * 4 + (threadIdx.x >> 5);
    int l = threadIdx.x & 31;
    if (row >= M) return;
    float Mx = -1e30f, S = 0.f;
    for (int c = l; c < 250; c += 32) {
        float m2 = pmax[(size_t)c * 4096 + row];
        float s2 = psum[(size_t)c * 4096 + row];
        float Mn = fmaxf(Mx, m2);
        S = S * expf(Mx - Mn) + s2 * expf(m2 - Mn);
        Mx = Mn;
    }
    #pragma unroll
    for (int m = 16; m > 0; m >>= 1) {
        float M2 = __shfl_xor_sync(0xffffffff, Mx, m);
        float S2 = __shfl_xor_sync(0xffffffff, S, m);
        float Mn = fmaxf(Mx, M2);
        S = S * expf(Mx - Mn) + S2 * expf(M2 - Mn);
        Mx = Mn;
    }
    if (l == 0) lse[row] = Mx + logf(S);
}

// gold[row] = outs[row] . W_vocab[target[row+64]]  (one warp per row)
__global__ void gold_k(const float* __restrict__ outs, const float* __restrict__ Wv,
                       const int* __restrict__ tgt, float* __restrict__ gold, int M) {
    int row = blockIdx.x * 4 + (threadIdx.x >> 5);
    int l = threadIdx.x & 31;
    if (row >= M) return;
    int id = tgt[row + 64];
    const float* a = outs + (size_t)row * HH;
    const float* w = Wv + (size_t)id * HH;
    float s = 0.f;
    for (int k = l; k < HH; k += 32) s += a[k] * w[k];
    #pragma unroll
    for (int m = 16; m > 0; m >>= 1) s += __shfl_xor_sync(0xffffffff, s, m);
    if (l == 0) gold[row] = s;
}

__global__ void final_k(const float* __restrict__ gold, const float* __restrict__ lse,
                        const int* __restrict__ tgt, float* __restrict__ out) {
    int b = threadIdx.x;
    if (b >= BB) return;
    float s = 0.f;
    for (int t = 0; t < TD; t++) {
        int r = t * BB + b;
        if (tgt[r + 64] != 0) s += gold[r] - lse[r];
    }
    out[b] = s;
}

// ---------------- host launch ----------------
extern "C" void kernel_launch(void* const* d_in, const int* in_sizes, int n_in,
                              void* d_out, int out_size) {
    const int*   src_pad = (const int*)  d_in[0];
    const int*   tgt_pad = (const int*)  d_in[1];
    const int*   lens    = (const int*)  d_in[2];
    const float* src_emb = (const float*)d_in[3];
    const float* dst_emb = (const float*)d_in[4];
    const float* Wihf = (const float*)d_in[5];
    const float* Whhf = (const float*)d_in[6];
    const float* bihf = (const float*)d_in[7];
    const float* bhhf = (const float*)d_in[8];
    const float* Wihb = (const float*)d_in[9];
    const float* Whhb = (const float*)d_in[10];
    const float* bihb = (const float*)d_in[11];
    const float* bhhb = (const float*)d_in[12];
    const float* Wihd = (const float*)d_in[13];
    const float* Whhd = (const float*)d_in[14];
    const float* bihd = (const float*)d_in[15];
    const float* bhhd = (const float*)d_in[16];
    const float* Whpr = (const float*)d_in[17];
    const float* Wcpr = (const float*)d_in[18];
    const float* Watt = (const float*)d_in[19];
    const float* Wcmb = (const float*)d_in[20];
    const float* Wvoc = (const float*)d_in[21];
    float* out = (float*)d_out;

    float* gb;
    cudaGetSymbolAddress((void**)&gb, g_buf);
    float* X    = gb + OFF_X;
    float* Y    = gb + OFF_Y;
    float* XF   = gb + OFF_XF;
    float* XB   = gb + OFF_XB;
    float* YW   = gb + OFF_YW;
    float* OUTF = gb + OFF_OUTF;
    float* OUTB = gb + OFF_OUTB;
    float* ENCH = gb + OFF_ENCH;
    float* ENCP = gb + OFF_ENCP;
    float* OUTS = gb + OFF_OUTS;
    float* Hb   = gb + OFF_H;
    float* Cb   = gb + OFF_C;
    float* H0   = gb + OFF_H0;
    float* C0   = gb + OFF_C0;
    float* O0   = gb + OFF_O0;
    float* HCAT = gb + OFF_HCAT;
    float* CCAT = gb + OFF_CCAT;
    float* ATT  = gb + OFF_ATT;
    float* PART = gb + OFF_PART;
    float* BS   = gb + OFF_BS;
    float* GOLD = gb + OFF_GOLD;
    float* LSE  = gb + OFF_LSE;
    float* PMAX = gb + OFF_PMAX;
    float* PSUM = gb + OFF_PSUM;

    const size_t SS4 = (size_t)BB * H4;   // slot stride for N=4096
    const size_t SS1 = (size_t)BB * HH;   // slot stride for N=1024

    bias3_k<<<16, 256>>>(BS, bihf, bhhf, bihb, bhhb, bihd, bhhd);
    gather_k<<<TSRC*BB, 128>>>(X, src_emb, src_pad);
    gather_k<<<TD*BB, 128>>>(Y, dst_emb, tgt_pad);

    // x @ Wih^T + bias (both encoder dirs), y @ Wihd[:, :512]^T + bias
    sgemm128<<<dim3(32, 32), 256>>>(X, EE, Wihf, EE, XF, H4, TSRC*BB, EE, BS);
    sgemm128<<<dim3(32, 32), 256>>>(X, EE, Wihb, EE, XB, H4, TSRC*BB, EE, BS + H4);
    sgemm128<<<dim3(32, 32), 256>>>(Y, EE, Wihd, 3*EE, YW, H4, TD*BB, EE, BS + 2*H4);

    // forward encoder scan
    zero_k<<<512, 256>>>(Hb, 2 * BB * HH);   // H and C contiguous
    for (int t = 0; t < TSRC; t++) {
        pgemm<<<dim3(64, 4), 256>>>(Hb, HH, Whhf, HH, PART, H4, 256, SS4);
        cell_k<<<256, 256>>>(XF + (size_t)t * SS4, PART, 4, Hb, Cb,
                             OUTF + (size_t)t * SS1, lens, t);
    }
    copycat_k<<<256, 256>>>(HCAT, Hb, 0);
    copycat_k<<<256, 256>>>(CCAT, Cb, 0);

    // backward encoder scan
    zero_k<<<512, 256>>>(Hb, 2 * BB * HH);
    for (int tt = 0; tt < TSRC; tt++) {
        int t = TSRC - 1 - tt;
        pgemm<<<dim3(64, 4), 256>>>(Hb, HH, Whhb, HH, PART, H4, 256, SS4);
        cell_k<<<256, 256>>>(XB + (size_t)t * SS4, PART, 4, Hb, Cb,
                             OUTB + (size_t)t * SS1, lens, t);
    }
    copycat_k<<<256, 256>>>(HCAT, Hb, HH);
    copycat_k<<<256, 256>>>(CCAT, Cb, HH);

    ench_k<<<16384, 256>>>(ENCH, OUTF, OUTB);

    // h0 / c0 projections
    pgemm<<<dim3(16, 4), 256>>>(HCAT, 2*HH, Whpr, 2*HH, PART, HH, 512, SS1);
    sumsl_k<<<256, 256>>>(H0, PART, 4);
    pgemm<<<dim3(16, 4), 256>>>(CCAT, 2*HH, Wcpr, 2*HH, PART, HH, 512, SS1);
    sumsl_k<<<256, 256>>>(C0, PART, 4);

    // enc_proj = ench @ W_att^T
    sgemm128<<<dim3(8, 32), 256>>>(ENCH, 2*HH, Watt, 2*HH, ENCP, HH, TSRC*BB, 2*HH, nullptr);

    // decoder
    zero_k<<<256, 256>>>(O0, BB * HH);
    for (int t = 0; t < TD; t++) {
        const float* o_prev = (t == 0) ? O0 : OUTS + (size_t)(t - 1) * SS1;
        pgemm<<<dim3(64, 4), 256>>>(H0, HH, Whhd, HH, PART, H4, 256, SS4);
        pgemm<<<dim3(64, 4), 256>>>(o_prev, HH, Wihd + EE, 3*EE, PART + 4*SS4, H4, 256, SS4);
        cell_k<<<256, 256>>>(YW + (size_t)t * SS4, PART, 8, H0, C0, nullptr, nullptr, 0);
        att_k<<<64, 256>>>(ENCP, ENCH, H0, lens, ATT);
        pgemm<<<dim3(16, 6), 256>>>(ATT, 3*HH, Wcmb, 3*HH, PART, HH, 512, SS1);
        tanhsum_k<<<256, 256>>>(OUTS + (size_t)t * SS1, PART, 6);
    }

    // vocab: fused streaming logsumexp + exact gold dot
    vgemm<<<dim3(250, 32), 256>>>(OUTS, Wvoc, PMAX, PSUM, TD*BB);
    lse_k<<<1008, 128>>>(PMAX, PSUM, LSE, TD*BB);
    gold_k<<<1008, 128>>>(OUTS, Wvoc, tgt_pad, GOLD, TD*BB);
    final_k<<<1, 64>>>(GOLD, LSE, tgt_pad, out);
}

// round 3
// speedup vs baseline: 1.1759x; 1.1759x over previous
#include <cuda_runtime.h>
#include <math.h>
#include <stdint.h>

#define TSRC 64
#define BB   64
#define EE   512
#define HH   1024
#define H4   4096
#define VV   32000
#define TD   63   // decoder steps

// ---------------- scratch layout (floats) ----------------
constexpr size_t SZ_X    = (size_t)TSRC*BB*EE;
constexpr size_t SZ_Y    = (size_t)TD*BB*EE;
constexpr size_t SZ_XF   = (size_t)TSRC*BB*H4;
constexpr size_t SZ_YW   = (size_t)TD*BB*H4;
constexpr size_t SZ_OUTH = (size_t)TSRC*BB*HH;
constexpr size_t SZ_ENCH = (size_t)BB*TSRC*2*HH;
constexpr size_t SZ_ENCP = (size_t)BB*TSRC*HH;
constexpr size_t SZ_OUTS = (size_t)TD*BB*HH;
constexpr size_t SZ_BH   = (size_t)BB*HH;
constexpr size_t SZ_CAT2 = (size_t)BB*2*HH;
constexpr size_t SZ_CAT3 = (size_t)BB*3*HH;
constexpr size_t SZ_PART = (size_t)12*BB*H4;
constexpr size_t SZ_BS   = (size_t)3*H4;
constexpr size_t SZ_ROWS = (size_t)4096;
constexpr size_t SZ_PM   = (size_t)250*4096;

constexpr size_t OFF_X    = 0;
constexpr size_t OFF_Y    = OFF_X    + SZ_X;
constexpr size_t OFF_XF   = OFF_Y    + SZ_Y;
constexpr size_t OFF_XB   = OFF_XF   + SZ_XF;
constexpr size_t OFF_YW   = OFF_XB   + SZ_XF;
constexpr size_t OFF_OUTF = OFF_YW   + SZ_YW;
constexpr size_t OFF_OUTB = OFF_OUTF + SZ_OUTH;
constexpr size_t OFF_ENCH = OFF_OUTB + SZ_OUTH;
constexpr size_t OFF_ENCP = OFF_ENCH + SZ_ENCH;
constexpr size_t OFF_OUTS = OFF_ENCP + SZ_ENCP;
constexpr size_t OFF_H    = OFF_OUTS + SZ_OUTS;
constexpr size_t OFF_C    = OFF_H    + SZ_BH;
constexpr size_t OFF_H0   = OFF_C    + SZ_BH;
constexpr size_t OFF_C0   = OFF_H0   + SZ_BH;
constexpr size_t OFF_O0   = OFF_C0   + SZ_BH;
constexpr size_t OFF_HCAT = OFF_O0   + SZ_BH;
constexpr size_t OFF_CCAT = OFF_HCAT + SZ_CAT2;
constexpr size_t OFF_ATT  = OFF_CCAT + SZ_CAT2;
constexpr size_t OFF_PART = OFF_ATT  + SZ_CAT3;
constexpr size_t OFF_BS   = OFF_PART + SZ_PART;
constexpr size_t OFF_GOLD = OFF_BS   + SZ_BS;
constexpr size_t OFF_LSE  = OFF_GOLD + SZ_ROWS;
constexpr size_t OFF_PMAX = OFF_LSE  + SZ_ROWS;
constexpr size_t OFF_PSUM = OFF_PMAX + SZ_PM;
constexpr size_t TOTAL    = OFF_PSUM + SZ_PM;

__device__ float g_buf[TOTAL];

__device__ __forceinline__ float sigm(float x) { return 1.0f / (1.0f + expf(-x)); }

__device__ __forceinline__ float f2tf(float x) {
    uint32_t r;
    asm("cvt.rna.tf32.f32 %0, %1;" : "=r"(r) : "f"(x));
    return __uint_as_float(r);
}

// ---------------- utility kernels ----------------
__global__ void zero_k(float* p, int n) {
    int i = blockIdx.x * blockDim.x + threadIdx.x;
    if (i < n) p[i] = 0.f;
}

__global__ void bias3_k(float* bs,
                        const float* __restrict__ a1, const float* __restrict__ a2,
                        const float* __restrict__ b1, const float* __restrict__ b2,
                        const float* __restrict__ c1, const float* __restrict__ c2) {
    int j = blockIdx.x * 256 + threadIdx.x;
    if (j < H4) {
        bs[j]        = a1[j] + a2[j];
        bs[H4 + j]   = b1[j] + b2[j];
        bs[2*H4 + j] = c1[j] + c2[j];
    }
}

__global__ void gather_k(float* __restrict__ out, const float* __restrict__ emb,
                         const int* __restrict__ idx) {
    int row = blockIdx.x;
    int id  = idx[row];
    const float4* s = (const float4*)(emb + (size_t)id * EE);
    float4* d = (float4*)(out + (size_t)row * EE);
    d[threadIdx.x] = s[threadIdx.x];
}

__global__ void copycat_k(float* __restrict__ dst, const float* __restrict__ src, int off) {
    int idx = blockIdx.x * 256 + threadIdx.x;
    int b = idx >> 10, j = idx & 1023;
    dst[(size_t)b * 2048 + off + j] = src[idx];
}

__global__ void ench_k(float* __restrict__ ench, const float* __restrict__ outf,
                       const float* __restrict__ outb) {
    int idx = blockIdx.x * 256 + threadIdx.x;
    int t = idx >> 16;
    int r = idx & 65535;
    int b = r >> 10, j = r & 1023;
    size_t dst = (size_t)b * (TSRC*2*HH) + (size_t)t * 2*HH + j;
    ench[dst]      = outf[idx];
    ench[dst + HH] = outb[idx];
}

__global__ void sumsl_k(float* __restrict__ dst, const float* __restrict__ part, int ns) {
    int idx = blockIdx.x * 256 + threadIdx.x;
    float s = 0.f;
    for (int q = 0; q < ns; q++) s += part[(size_t)q * 65536 + idx];
    dst[idx] = s;
}

__global__ void tanhsum_k(float* __restrict__ dst, const float* __restrict__ part, int ns) {
    int idx = blockIdx.x * 256 + threadIdx.x;
    float s = 0.f;
    for (int q = 0; q < ns; q++) s += part[(size_t)q * 65536 + idx];
    dst[idx] = tanhf(s);
}

// ================= TF32 tensor-core GEMM =================
// C[m,n] = sum_k A[m*lda+k] * B[n*ldb+k] (+bias[n]).
// Block tile 128x128, K-step 32, 8 warps (4 m x 2 n), warp tile 32x64.
// Shared layout: [row][32] with k permuted inside each group of 8:
//   storage pos for k' = k&7:  (k'<4) ? 2k' : 2(k'-4)+1
// so the mma fragment (k=t, k=t+4) is a single float2 at pos 2t.
// Row stride padded to 40 floats -> conflict-free float2 fragment loads.
// If FUSED: instead of storing C, emit per-row (max, sumexp) over this
// 128-col chunk into pmax/psum[chunk*4096 + row].
#define SSTR 40

template<bool FUSED>
__global__ __launch_bounds__(256)
void tgemm(const float* __restrict__ A, int lda,
           const float* __restrict__ B, int ldb,
           float* __restrict__ C, int ldc,
           int M, int K, const float* __restrict__ bias,
           float* __restrict__ pmax, float* __restrict__ psum) {
    __shared__ float As[128 * SSTR];
    __shared__ float Bs[128 * SSTR];
    __shared__ float smx[2][128];
    __shared__ float sms[2][128];

    const int bm = blockIdx.y * 128;
    const int bn = blockIdx.x * 128;
    const int tid  = threadIdx.x;
    const int lane = tid & 31;
    const int wid  = tid >> 5;
    const int wm   = (wid >> 1) * 32;   // warp m offset
    const int wn   = (wid & 1) * 64;    // warp n offset
    const int g    = lane >> 2;         // 0..7
    const int t    = lane & 3;          // 0..3

    float acc[2][8][4];
    #pragma unroll
    for (int i = 0; i < 2; i++)
        #pragma unroll
        for (int j = 0; j < 8; j++)
            #pragma unroll
            for (int r = 0; r < 4; r++) acc[i][j][r] = 0.f;

    for (int kt = 0; kt < K; kt += 32) {
        // ---- load A,B tiles (128 rows x 32 k) with k-permute + tf32 cvt ----
        #pragma unroll
        for (int q = 0; q < 4; q++) {
            int f   = q * 256 + tid;      // float4 index 0..1023
            int row = f >> 3;
            int c4  = (f & 7) << 2;       // k local base
            // A
            {
                int gr = bm + row;
                float4 v = make_float4(0.f,0.f,0.f,0.f);
                if (gr < M) v = *(const float4*)(A + (size_t)gr * lda + kt + c4);
                float vv[4] = {v.x, v.y, v.z, v.w};
                #pragma unroll
                for (int e = 0; e < 4; e++) {
                    int kl = c4 + e;
                    int grp = kl >> 3, kp = kl & 7;
                    int pos = (kp < 4) ? (kp << 1) : (((kp - 4) << 1) | 1);
                    As[row * SSTR + grp * 8 + pos] = f2tf(vv[e]);
                }
            }
            // B
            {
                int gr = bn + row;
                float4 v = *(const float4*)(B + (size_t)gr * ldb + kt + c4);
                float vv[4] = {v.x, v.y, v.z, v.w};
                #pragma unroll
                for (int e = 0; e < 4; e++) {
                    int kl = c4 + e;
                    int grp = kl >> 3, kp = kl & 7;
                    int pos = (kp < 4) ? (kp << 1) : (((kp - 4) << 1) | 1);
                    Bs[row * SSTR + grp * 8 + pos] = f2tf(vv[e]);
                }
            }
        }
        __syncthreads();

        #pragma unroll
        for (int kk = 0; kk < 4; kk++) {
            // B fragments: 8 n-tiles x (b0,b1)
            uint32_t bf[8][2];
            #pragma unroll
            for (int j = 0; j < 8; j++) {
                float2 b01 = *(const float2*)&Bs[(wn + j*8 + g) * SSTR + kk*8 + 2*t];
                bf[j][0] = __float_as_uint(b01.x);
                bf[j][1] = __float_as_uint(b01.y);
            }
            #pragma unroll
            for (int i = 0; i < 2; i++) {
                int ra = wm + i*16 + g;
                float2 a02 = *(const float2*)&As[ra       * SSTR + kk*8 + 2*t];
                float2 a13 = *(const float2*)&As[(ra + 8) * SSTR + kk*8 + 2*t];
                uint32_t a0 = __float_as_uint(a02.x);
                uint32_t a1 = __float_as_uint(a13.x);
                uint32_t a2 = __float_as_uint(a02.y);
                uint32_t a3 = __float_as_uint(a13.y);
                #pragma unroll
                for (int j = 0; j < 8; j++) {
                    asm volatile(
                        "mma.sync.aligned.m16n8k8.row.col.f32.tf32.tf32.f32 "
                        "{%0,%1,%2,%3}, {%4,%5,%6,%7}, {%8,%9}, {%0,%1,%2,%3};"
                        : "+f"(acc[i][j][0]), "+f"(acc[i][j][1]),
                          "+f"(acc[i][j][2]), "+f"(acc[i][j][3])
                        : "r"(a0), "r"(a1), "r"(a2), "r"(a3),
                          "r"(bf[j][0]), "r"(bf[j][1]));
                }
            }
        }
        __syncthreads();
    }

    if (!FUSED) {
        // store C (+bias). cols for (c0,c1) are adjacent -> float2 stores.
        #pragma unroll
        for (int i = 0; i < 2; i++) {
            int r0 = bm + wm + i*16 + g;
            int r1 = r0 + 8;
            #pragma unroll
            for (int j = 0; j < 8; j++) {
                int col = bn + wn + j*8 + 2*t;
                float b0 = bias ? bias[col]   : 0.f;
                float b1 = bias ? bias[col+1] : 0.f;
                if (r0 < M) {
                    float2 v = make_float2(acc[i][j][0] + b0, acc[i][j][1] + b1);
                    *(float2*)(C + (size_t)r0 * ldc + col) = v;
                }
                if (r1 < M) {
                    float2 v = make_float2(acc[i][j][2] + b0, acc[i][j][3] + b1);
                    *(float2*)(C + (size_t)r1 * ldc + col) = v;
                }
            }
        }
    } else {
        // per-row (max, sumexp) over the 128-col chunk
        #pragma unroll
        for (int i = 0; i < 2; i++) {
            #pragma unroll
            for (int half = 0; half < 2; half++) {
                float mx = -1e30f;
                #pragma unroll
                for (int j = 0; j < 8; j++) {
                    mx = fmaxf(mx, acc[i][j][half*2+0]);
                    mx = fmaxf(mx, acc[i][j][half*2+1]);
                }
                float s = 0.f;
                #pragma unroll
                for (int j = 0; j < 8; j++) {
                    s += expf(acc[i][j][half*2+0] - mx);
                    s += expf(acc[i][j][half*2+1] - mx);
                }
                // combine across the 4 t-lanes (lane = 4g + t)
                #pragma unroll
                for (int m = 1; m < 4; m <<= 1) {
                    float M2 = __shfl_xor_sync(0xffffffff, mx, m);
                    float S2 = __shfl_xor_sync(0xffffffff, s,  m);
                    float Mn = fmaxf(mx, M2);
                    s = s * expf(mx - Mn) + S2 * expf(M2 - Mn);
                    mx = Mn;
                }
                if (t == 0) {
                    int rloc = wm + i*16 + half*8 + g;
                    smx[wid & 1][rloc] = mx;
                    sms[wid & 1][rloc] = s;
                }
            }
        }
        __syncthreads();
        if (tid < 128) {
            int gm = bm + tid;
            if (gm < M) {
                float m0 = smx[0][tid], m1 = smx[1][tid];
                float Mn = fmaxf(m0, m1);
                float S  = sms[0][tid] * expf(m0 - Mn) + sms[1][tid] * expf(m1 - Mn);
                int chunk = blockIdx.x;
                pmax[(size_t)chunk * 4096 + gm] = Mn;
                psum[(size_t)chunk * 4096 + gm] = S;
            }
        }
    }
}

// ---------------- small-M (M=64) partial GEMM, K-split ----------------
__global__ __launch_bounds__(256)
void pgemm(const float* __restrict__ A, int lda,
           const float* __restrict__ W, int ldw,
           float* __restrict__ out, int Ntot, int Kper, size_t slotStride) {
    __shared__ float As[16][68];
    __shared__ float Ws[16][68];
    const int bn = blockIdx.x * 64;
    const int s  = blockIdx.y;
    const int k0 = s * Kper;
    out += (size_t)s * slotStride;
    const int tid = threadIdx.x;
    const int lr = tid >> 2;
    const int lc = (tid & 3) << 2;
    const int ty = tid >> 4;
    const int tx = tid & 15;
    float acc[4][4];
    #pragma unroll
    for (int i = 0; i < 4; i++)
        #pragma unroll
        for (int j = 0; j < 4; j++) acc[i][j] = 0.f;

    for (int kt = k0; kt < k0 + Kper; kt += 16) {
        float4 v = *(const float4*)(A + (size_t)lr * lda + kt + lc);
        As[lc+0][lr] = v.x; As[lc+1][lr] = v.y; As[lc+2][lr] = v.z; As[lc+3][lr] = v.w;
        float4 w = *(const float4*)(W + (size_t)(bn + lr) * ldw + kt + lc);
        Ws[lc+0][lr] = w.x; Ws[lc+1][lr] = w.y; Ws[lc+2][lr] = w.z; Ws[lc+3][lr] = w.w;
        __syncthreads();
        #pragma unroll
        for (int k = 0; k < 16; k++) {
            float4 a = *(const float4*)&As[k][ty*4];
            float4 b = *(const float4*)&Ws[k][tx*4];
            float av[4] = {a.x,a.y,a.z,a.w};
            float bv[4] = {b.x,b.y,b.z,b.w};
            #pragma unroll
            for (int i = 0; i < 4; i++)
                #pragma unroll
                for (int j = 0; j < 4; j++) acc[i][j] += av[i] * bv[j];
        }
        __syncthreads();
    }
    #pragma unroll
    for (int i = 0; i < 4; i++) {
        int b = ty * 4 + i;
        #pragma unroll
        for (int j = 0; j < 4; j++)
            out[(size_t)b * Ntot + bn + tx * 4 + j] = acc[i][j];
    }
}

// ---------------- LSTM cell ----------------
__global__ void cell_k(const float* __restrict__ X, const float* __restrict__ part,
                       int ns, float* __restrict__ h, float* __restrict__ c,
                       float* __restrict__ outp, const int* __restrict__ lens, int t) {
    int idx = blockIdx.x * 256 + threadIdx.x;
    int b = idx >> 10, j = idx & 1023;
    size_t base = (size_t)b * H4 + j;
    float gi = X[base], gf = X[base + HH], gg = X[base + 2*HH], go = X[base + 3*HH];
    for (int q = 0; q < ns; q++) {
        const float* p = part + (size_t)q * (BB*H4);
        gi += p[base]; gf += p[base + HH]; gg += p[base + 2*HH]; go += p[base + 3*HH];
    }
    float cold = c[idx];
    float c2 = sigm(gf) * cold + sigm(gi) * tanhf(gg);
    float h2 = sigm(go) * tanhf(c2);
    bool m = lens ? (t < lens[b]) : true;
    h[idx] = m ? h2 : h[idx];
    c[idx] = m ? c2 : cold;
    if (outp) outp[idx] = m ? h2 : 0.f;
}

// ---------------- attention ----------------
__global__ __launch_bounds__(256)
void att_k(const float* __restrict__ encp, const float* __restrict__ ench,
           const float* __restrict__ h, const int* __restrict__ lens,
           float* __restrict__ cat) {
    __shared__ float e[64];
    __shared__ float alpha[64];
    const int b = blockIdx.x;
    const int tid = threadIdx.x;
    const int w = tid >> 5, l = tid & 31;
    const int len = lens[b];
    for (int t = w; t < 64; t += 8) {
        const float* ep = encp + ((size_t)b * 64 + t) * HH;
        const float* hp = h + (size_t)b * HH;
        float s = 0.f;
        for (int k = l; k < HH; k += 32) s += ep[k] * hp[k];
        #pragma unroll
        for (int m = 16; m > 0; m >>= 1) s += __shfl_xor_sync(0xffffffff, s, m);
        if (l == 0) e[t] = s;
    }
    __syncthreads();
    if (tid == 0) {
        float mx = -1e30f;
        for (int t = 0; t < len; t++) mx = fmaxf(mx, e[t]);
        float sm = 0.f;
        for (int t = 0; t < len; t++) sm += expf(e[t] - mx);
        float inv = 1.f / sm;
        for (int t = 0; t < 64; t++) alpha[t] = (t < len) ? expf(e[t] - mx) * inv : 0.f;
    }
    __syncthreads();
    const float* eh = ench + (size_t)b * (64 * 2048);
    for (int d = tid; d < 2048; d += 256) {
        float s = 0.f;
        for (int t = 0; t < len; t++) s += alpha[t] * eh[(size_t)t * 2048 + d];
        cat[(size_t)b * 3072 + d] = s;
    }
    for (int d = tid; d < 1024; d += 256)
        cat[(size_t)b * 3072 + 2048 + d] = h[(size_t)b * HH + d];
}

// ---------------- lse over 250 chunks ----------------
__global__ void lse_k(const float* __restrict__ pmax, const float* __restrict__ psum,
                      float* __restrict__ lse, int M) {
    int row = blockIdx.x * 4 + (threadIdx.x >> 5);
    int l = threadIdx.x & 31;
    if (row >= M) return;
    float Mx = -1e30f, S = 0.f;
    for (int c = l; c < 250; c += 32) {
        float m2 = pmax[(size_t)c * 4096 + row];
        float s2 = psum[(size_t)c * 4096 + row];
        float Mn = fmaxf(Mx, m2);
        S = S * expf(Mx - Mn) + s2 * expf(m2 - Mn);
        Mx = Mn;
    }
    #pragma unroll
    for (int m = 16; m > 0; m >>= 1) {
        float M2 = __shfl_xor_sync(0xffffffff, Mx, m);
        float S2 = __shfl_xor_sync(0xffffffff, S, m);
        float Mn = fmaxf(Mx, M2);
        S = S * expf(Mx - Mn) + S2 * expf(M2 - Mn);
        Mx = Mn;
    }
    if (l == 0) lse[row] = Mx + logf(S);
}

// gold[row] = outs[row] . W_vocab[target[row+64]]
__global__ void gold_k(const float* __restrict__ outs, const float* __restrict__ Wv,
                       const int* __restrict__ tgt, float* __restrict__ gold, int M) {
    int row = blockIdx.x * 4 + (threadIdx.x >> 5);
    int l = threadIdx.x & 31;
    if (row >= M) return;
    int id = tgt[row + 64];
    const float* a = outs + (size_t)row * HH;
    const float* w = Wv + (size_t)id * HH;
    float s = 0.f;
    for (int k = l; k < HH; k += 32) {
        // match vocab GEMM precision: tf32 both operands
        s += f2tf(a[k]) * f2tf(w[k]);
    }
    #pragma unroll
    for (int m = 16; m > 0; m >>= 1) s += __shfl_xor_sync(0xffffffff, s, m);
    if (l == 0) gold[row] = s;
}

__global__ void final_k(const float* __restrict__ gold, const float* __restrict__ lse,
                        const int* __restrict__ tgt, float* __restrict__ out) {
    int b = threadIdx.x;
    if (b >= BB) return;
    float s = 0.f;
    for (int t = 0; t < TD; t++) {
        int r = t * BB + b;
        if (tgt[r + 64] != 0) s += gold[r] - lse[r];
    }
    out[b] = s;
}

// ---------------- host launch ----------------
extern "C" void kernel_launch(void* const* d_in, const int* in_sizes, int n_in,
                              void* d_out, int out_size) {
    const int*   src_pad = (const int*)  d_in[0];
    const int*   tgt_pad = (const int*)  d_in[1];
    const int*   lens    = (const int*)  d_in[2];
    const float* src_emb = (const float*)d_in[3];
    const float* dst_emb = (const float*)d_in[4];
    const float* Wihf = (const float*)d_in[5];
    const float* Whhf = (const float*)d_in[6];
    const float* bihf = (const float*)d_in[7];
    const float* bhhf = (const float*)d_in[8];
    const float* Wihb = (const float*)d_in[9];
    const float* Whhb = (const float*)d_in[10];
    const float* bihb = (const float*)d_in[11];
    const float* bhhb = (const float*)d_in[12];
    const float* Wihd = (const float*)d_in[13];
    const float* Whhd = (const float*)d_in[14];
    const float* bihd = (const float*)d_in[15];
    const float* bhhd = (const float*)d_in[16];
    const float* Whpr = (const float*)d_in[17];
    const float* Wcpr = (const float*)d_in[18];
    const float* Watt = (const float*)d_in[19];
    const float* Wcmb = (const float*)d_in[20];
    const float* Wvoc = (const float*)d_in[21];
    float* out = (float*)d_out;

    float* gb;
    cudaGetSymbolAddress((void**)&gb, g_buf);
    float* X    = gb + OFF_X;
    float* Y    = gb + OFF_Y;
    float* XF   = gb + OFF_XF;
    float* XB   = gb + OFF_XB;
    float* YW   = gb + OFF_YW;
    float* OUTF = gb + OFF_OUTF;
    float* OUTB = gb + OFF_OUTB;
    float* ENCH = gb + OFF_ENCH;
    float* ENCP = gb + OFF_ENCP;
    float* OUTS = gb + OFF_OUTS;
    float* Hb   = gb + OFF_H;
    float* Cb   = gb + OFF_C;
    float* H0   = gb + OFF_H0;
    float* C0   = gb + OFF_C0;
    float* O0   = gb + OFF_O0;
    float* HCAT = gb + OFF_HCAT;
    float* CCAT = gb + OFF_CCAT;
    float* ATT  = gb + OFF_ATT;
    float* PART = gb + OFF_PART;
    float* BS   = gb + OFF_BS;
    float* GOLD = gb + OFF_GOLD;
    float* LSE  = gb + OFF_LSE;
    float* PMAX = gb + OFF_PMAX;
    float* PSUM = gb + OFF_PSUM;

    const size_t SS4 = (size_t)BB * H4;
    const size_t SS1 = (size_t)BB * HH;

    bias3_k<<<16, 256>>>(BS, bihf, bhhf, bihb, bhhb, bihd, bhhd);
    gather_k<<<TSRC*BB, 128>>>(X, src_emb, src_pad);
    gather_k<<<TD*BB, 128>>>(Y, dst_emb, tgt_pad);

    // x @ Wih^T + bias (TF32 tensor cores)
    tgemm<false><<<dim3(32, 32), 256>>>(X, EE, Wihf, EE, XF, H4, TSRC*BB, EE, BS, nullptr, nullptr);
    tgemm<false><<<dim3(32, 32), 256>>>(X, EE, Wihb, EE, XB, H4, TSRC*BB, EE, BS + H4, nullptr, nullptr);
    tgemm<false><<<dim3(32, 32), 256>>>(Y, EE, Wihd, 3*EE, YW, H4, TD*BB, EE, BS + 2*H4, nullptr, nullptr);

    // forward encoder scan
    zero_k<<<512, 256>>>(Hb, 2 * BB * HH);
    for (int t = 0; t < TSRC; t++) {
        pgemm<<<dim3(64, 4), 256>>>(Hb, HH, Whhf, HH, PART, H4, 256, SS4);
        cell_k<<<256, 256>>>(XF + (size_t)t * SS4, PART, 4, Hb, Cb,
                             OUTF + (size_t)t * SS1, lens, t);
    }
    copycat_k<<<256, 256>>>(HCAT, Hb, 0);
    copycat_k<<<256, 256>>>(CCAT, Cb, 0);

    // backward encoder scan
    zero_k<<<512, 256>>>(Hb, 2 * BB * HH);
    for (int tt = 0; tt < TSRC; tt++) {
        int t = TSRC - 1 - tt;
        pgemm<<<dim3(64, 4), 256>>>(Hb, HH, Whhb, HH, PART, H4, 256, SS4);
        cell_k<<<256, 256>>>(XB + (size_t)t * SS4, PART, 4, Hb, Cb,
                             OUTB + (size_t)t * SS1, lens, t);
    }
    copycat_k<<<256, 256>>>(HCAT, Hb, HH);
    copycat_k<<<256, 256>>>(CCAT, Cb, HH);

    ench_k<<<16384, 256>>>(ENCH, OUTF, OUTB);

    // h0 / c0 projections
    pgemm<<<dim3(16, 4), 256>>>(HCAT, 2*HH, Whpr, 2*HH, PART, HH, 512, SS1);
    sumsl_k<<<256, 256>>>(H0, PART, 4);
    pgemm<<<dim3(16, 4), 256>>>(CCAT, 2*HH, Wcpr, 2*HH, PART, HH, 512, SS1);
    sumsl_k<<<256, 256>>>(C0, PART, 4);

    // enc_proj = ench @ W_att^T (TF32)
    tgemm<false><<<dim3(8, 32), 256>>>(ENCH, 2*HH, Watt, 2*HH, ENCP, HH, TSRC*BB, 2*HH, nullptr, nullptr, nullptr);

    // decoder
    zero_k<<<256, 256>>>(O0, BB * HH);
    for (int t = 0; t < TD; t++) {
        const float* o_prev = (t == 0) ? O0 : OUTS + (size_t)(t - 1) * SS1;
        pgemm<<<dim3(64, 4), 256>>>(H0, HH, Whhd, HH, PART, H4, 256, SS4);
        pgemm<<<dim3(64, 4), 256>>>(o_prev, HH, Wihd + EE, 3*EE, PART + 4*SS4, H4, 256, SS4);
        cell_k<<<256, 256>>>(YW + (size_t)t * SS4, PART, 8, H0, C0, nullptr, nullptr, 0);
        att_k<<<64, 256>>>(ENCP, ENCH, H0, lens, ATT);
        pgemm<<<dim3(16, 6), 256>>>(ATT, 3*HH, Wcmb, 3*HH, PART, HH, 512, SS1);
        tanhsum_k<<<256, 256>>>(OUTS + (size_t)t * SS1, PART, 6);
    }

    // vocab: TF32 GEMM with fused streaming chunk stats + exact gold dot
    tgemm<true><<<dim3(250, 32), 256>>>(OUTS, HH, Wvoc, HH, nullptr, 0, TD*BB, HH, nullptr, PMAX, PSUM);
    lse_k<<<1008, 128>>>(PMAX, PSUM, LSE, TD*BB);
    gold_k<<<1008, 128>>>(OUTS, Wvoc, tgt_pad, GOLD, TD*BB);
    final_k<<<1, 64>>>(GOLD, LSE, tgt_pad, out);
}

// round 4
// speedup vs baseline: 1.9532x; 1.6609x over previous
#include <cuda_runtime.h>
#include <cuda_bf16.h>
#include <math.h>
#include <stdint.h>

#define TSRC 64
#define BB   64
#define EE   512
#define HH   1024
#define H4   4096
#define VV   32000
#define TD   63

// ---------------- fp32 scratch ----------------
constexpr size_t SZ_X    = (size_t)TSRC*BB*EE;
constexpr size_t SZ_Y    = (size_t)TD*BB*EE;
constexpr size_t SZ_XF   = (size_t)TSRC*BB*H4;
constexpr size_t SZ_YW   = (size_t)TD*BB*H4;
constexpr size_t SZ_OUTH = (size_t)TSRC*BB*HH;
constexpr size_t SZ_ENCH = (size_t)BB*TSRC*2*HH;
constexpr size_t SZ_ENCP = (size_t)BB*TSRC*HH;
constexpr size_t SZ_OUTS = (size_t)TD*BB*HH;
constexpr size_t SZ_BH   = (size_t)BB*HH;
constexpr size_t SZ_CAT2 = (size_t)BB*2*HH;
constexpr size_t SZ_CAT3 = (size_t)BB*3*HH;
constexpr size_t SZ_ACAT = (size_t)BB*2*HH;
constexpr size_t SZ_PART = (size_t)12*BB*H4;
constexpr size_t SZ_BS   = (size_t)3*H4;
constexpr size_t SZ_ROWS = (size_t)4096;
constexpr size_t SZ_PM   = (size_t)250*4096;

constexpr size_t OFF_X    = 0;
constexpr size_t OFF_Y    = OFF_X    + SZ_X;
constexpr size_t OFF_XF   = OFF_Y    + SZ_Y;
constexpr size_t OFF_XB   = OFF_XF   + SZ_XF;
constexpr size_t OFF_YW   = OFF_XB   + SZ_XF;
constexpr size_t OFF_OUTF = OFF_YW   + SZ_YW;
constexpr size_t OFF_OUTB = OFF_OUTF + SZ_OUTH;
constexpr size_t OFF_ENCH = OFF_OUTB + SZ_OUTH;
constexpr size_t OFF_ENCP = OFF_ENCH + SZ_ENCH;
constexpr size_t OFF_OUTS = OFF_ENCP + SZ_ENCP;
constexpr size_t OFF_H    = OFF_OUTS + SZ_OUTS;
constexpr size_t OFF_C    = OFF_H    + SZ_BH;
constexpr size_t OFF_H0   = OFF_C    + SZ_BH;
constexpr size_t OFF_C0   = OFF_H0   + SZ_BH;
constexpr size_t OFF_HCAT = OFF_C0   + SZ_BH;
constexpr size_t OFF_CCAT = OFF_HCAT + SZ_CAT2;
constexpr size_t OFF_ATT  = OFF_CCAT + SZ_CAT2;
constexpr size_t OFF_ACAT = OFF_ATT  + SZ_CAT3;
constexpr size_t OFF_PART = OFF_ACAT + SZ_ACAT;
constexpr size_t OFF_BS   = OFF_PART + SZ_PART;
constexpr size_t OFF_GOLD = OFF_BS   + SZ_BS;
constexpr size_t OFF_LSE  = OFF_GOLD + SZ_ROWS;
constexpr size_t OFF_PMAX = OFF_LSE  + SZ_ROWS;
constexpr size_t OFF_PSUM = OFF_PMAX + SZ_PM;
constexpr size_t TOTAL    = OFF_PSUM + SZ_PM;

__device__ float g_buf[TOTAL];

// ---------------- bf16 scratch ----------------
constexpr size_t BOFF_WVOC = 0;
constexpr size_t BOFF_WHHF = BOFF_WVOC + (size_t)VV*HH;
constexpr size_t BOFF_WHHB = BOFF_WHHF + (size_t)H4*HH;
constexpr size_t BOFF_WCAT = BOFF_WHHB + (size_t)H4*HH;
constexpr size_t BOFF_WIHF = BOFF_WCAT + (size_t)H4*2*HH;
constexpr size_t BOFF_WIHB = BOFF_WIHF + (size_t)H4*EE;
constexpr size_t BOFF_WIHDY= BOFF_WIHB + (size_t)H4*EE;
constexpr size_t BOFF_WATT = BOFF_WIHDY+ (size_t)H4*EE;
constexpr size_t BOFF_WCMB = BOFF_WATT + (size_t)HH*2*HH;
constexpr size_t BTOTAL    = BOFF_WCMB + (size_t)HH*3*HH;

__device__ __nv_bfloat16 g_bf[BTOTAL];

__device__ __forceinline__ float sigm(float x) { return 1.0f / (1.0f + expf(-x)); }

// pack (lo, hi) floats into one bf16x2 register (lo = lower address)
__device__ __forceinline__ uint32_t packbf(float lo, float hi) {
    uint32_t r;
    asm("cvt.rn.bf16x2.f32 %0, %1, %2;" : "=r"(r) : "f"(hi), "f"(lo));
    return r;
}

// ---------------- utility kernels ----------------
__global__ void zero_k(float* p, int n) {
    int i = blockIdx.x * blockDim.x + threadIdx.x;
    if (i < n) p[i] = 0.f;
}

__global__ void bias3_k(float* bs,
                        const float* __restrict__ a1, const float* __restrict__ a2,
                        const float* __restrict__ b1, const float* __restrict__ b2,
                        const float* __restrict__ c1, const float* __restrict__ c2) {
    int j = blockIdx.x * 256 + threadIdx.x;
    if (j < H4) {
        bs[j]        = a1[j] + a2[j];
        bs[H4 + j]   = b1[j] + b2[j];
        bs[2*H4 + j] = c1[j] + c2[j];
    }
}

__global__ void gather_k(float* __restrict__ out, const float* __restrict__ emb,
                         const int* __restrict__ idx) {
    int row = blockIdx.x;
    int id  = idx[row];
    const float4* s = (const float4*)(emb + (size_t)id * EE);
    float4* d = (float4*)(out + (size_t)row * EE);
    d[threadIdx.x] = s[threadIdx.x];
}

// strided fp32 -> bf16 (4 per thread)
__global__ void cvt_rows(__nv_bfloat16* __restrict__ dst, const float* __restrict__ src,
                         int rows, int cols, int srcStride) {
    size_t n4 = (size_t)rows * cols / 4;
    size_t i = (size_t)blockIdx.x * 256 + threadIdx.x;
    if (i >= n4) return;
    size_t e = i * 4;
    int r = (int)(e / cols), c = (int)(e % cols);
    float4 v = *(const float4*)(src + (size_t)r * srcStride + c);
    uint32_t p0 = packbf(v.x, v.y);
    uint32_t p1 = packbf(v.z, v.w);
    *(uint32_t*)(dst + e)     = p0;
    *(uint32_t*)(dst + e + 2) = p1;
}

// Wcat[n][0:1024] = Whhd[n][:], Wcat[n][1024:2048] = Wihd[n][512:1536]
__global__ void cvt_cat(__nv_bfloat16* __restrict__ dst, const float* __restrict__ whh,
                        const float* __restrict__ wih) {
    size_t i = (size_t)blockIdx.x * 256 + threadIdx.x;   // over H4*2048/4
    if (i >= (size_t)H4 * 2048 / 4) return;
    size_t e = i * 4;
    int n = (int)(e >> 11), j = (int)(e & 2047);
    float4 v;
    if (j < 1024) v = *(const float4*)(whh + (size_t)n * HH + j);
    else          v = *(const float4*)(wih + (size_t)n * 1536 + 512 + (j - 1024));
    *(uint32_t*)(dst + e)     = packbf(v.x, v.y);
    *(uint32_t*)(dst + e + 2) = packbf(v.z, v.w);
}

__global__ void copycat_k(float* __restrict__ dst, const float* __restrict__ src, int off) {
    int idx = blockIdx.x * 256 + threadIdx.x;
    int b = idx >> 10, j = idx & 1023;
    dst[(size_t)b * 2048 + off + j] = src[idx];
}

__global__ void ench_k(float* __restrict__ ench, const float* __restrict__ outf,
                       const float* __restrict__ outb) {
    int idx = blockIdx.x * 256 + threadIdx.x;
    int t = idx >> 16;
    int r = idx & 65535;
    int b = r >> 10, j = r & 1023;
    size_t dst = (size_t)b * (TSRC*2*HH) + (size_t)t * 2*HH + j;
    ench[dst]      = outf[idx];
    ench[dst + HH] = outb[idx];
}

__global__ void sumsl_k(float* __restrict__ dst, const float* __restrict__ part, int ns) {
    int idx = blockIdx.x * 256 + threadIdx.x;
    float s = 0.f;
    for (int q = 0; q < ns; q++) s += part[(size_t)q * 65536 + idx];
    dst[idx] = s;
}

__global__ void cat_h(float* __restrict__ acat, const float* __restrict__ h0) {
    int idx = blockIdx.x * 256 + threadIdx.x;   // 65536
    int b = idx >> 10, j = idx & 1023;
    acat[(size_t)b * 2048 + j] = h0[idx];
}

// tanh of summed slices -> OUTS + right half of ACAT
__global__ void tanhsum_k(float* __restrict__ dst, const float* __restrict__ part,
                          int ns, float* __restrict__ acat) {
    int idx = blockIdx.x * 256 + threadIdx.x;
    float s = 0.f;
    for (int q = 0; q < ns; q++) s += part[(size_t)q * 65536 + idx];
    float v = tanhf(s);
    dst[idx] = v;
    int b = idx >> 10, j = idx & 1023;
    acat[(size_t)b * 2048 + 1024 + j] = v;
}

// ================= bf16 tensor-core GEMM (big) =================
// C[m,n] = sum_k A[m*lda+k] * B[n*ldb+k] (+bias). A fp32, B bf16.
// 128x128 tile, K-chunk 64, 8 warps (4m x 2n), warp tile 32x64. K%64==0.
#define SASTR 72

template<bool FUSED>
__global__ __launch_bounds__(256)
void bgemm(const float* __restrict__ A, int lda,
           const __nv_bfloat16* __restrict__ B, int ldb,
           float* __restrict__ C, int ldc,
           int M, int K, const float* __restrict__ bias,
           float* __restrict__ pmax, float* __restrict__ psum) {
    __shared__ __align__(16) __nv_bfloat16 As[128 * SASTR];
    __shared__ __align__(16) __nv_bfloat16 Bs[128 * SASTR];
    __shared__ float smx[2][128];
    __shared__ float sms[2][128];

    const int bm = blockIdx.y * 128;
    const int bn = blockIdx.x * 128;
    const int tid  = threadIdx.x;
    const int lane = tid & 31;
    const int wid  = tid >> 5;
    const int wm   = (wid >> 1) * 32;
    const int wn   = (wid & 1) * 64;
    const int g    = lane >> 2;
    const int t    = lane & 3;

    float acc[2][8][4];
    #pragma unroll
    for (int i = 0; i < 2; i++)
        #pragma unroll
        for (int j = 0; j < 8; j++)
            #pragma unroll
            for (int r = 0; r < 4; r++) acc[i][j][r] = 0.f;

    for (int kt = 0; kt < K; kt += 64) {
        // A: 128 rows x 64 k fp32 -> bf16.  2048 float4 / 256 thr = 8 each.
        #pragma unroll
        for (int q = 0; q < 8; q++) {
            int f = q * 256 + tid;
            int row = f >> 4;
            int c4 = (f & 15) << 2;
            int gr = bm + row;
            float4 v = make_float4(0.f,0.f,0.f,0.f);
            if (gr < M) v = *(const float4*)(A + (size_t)gr * lda + kt + c4);
            *(uint32_t*)&As[row * SASTR + c4]     = packbf(v.x, v.y);
            *(uint32_t*)&As[row * SASTR + c4 + 2] = packbf(v.z, v.w);
        }
        // B: 128 rows x 64 k bf16.  1024 uint4 / 256 thr = 4 each.
        #pragma unroll
        for (int q = 0; q < 4; q++) {
            int f = q * 256 + tid;
            int row = f >> 3;
            int c8 = (f & 7) << 3;
            uint4 v = *(const uint4*)(B + (size_t)(bn + row) * ldb + kt + c8);
            *(uint4*)&Bs[row * SASTR + c8] = v;
        }
        __syncthreads();

        #pragma unroll
        for (int kk = 0; kk < 4; kk++) {
            uint32_t bf[8][2];
            #pragma unroll
            for (int j = 0; j < 8; j++) {
                int rb = (wn + j*8 + g) * SASTR + kk*16;
                bf[j][0] = *(const uint32_t*)&Bs[rb + 2*t];
                bf[j][1] = *(const uint32_t*)&Bs[rb + 8 + 2*t];
            }
            #pragma unroll
            for (int i = 0; i < 2; i++) {
                int ra0 = (wm + i*16 + g) * SASTR + kk*16;
                int ra1 = (wm + i*16 + 8 + g) * SASTR + kk*16;
                uint32_t a0 = *(const uint32_t*)&As[ra0 + 2*t];
                uint32_t a1 = *(const uint32_t*)&As[ra1 + 2*t];
                uint32_t a2 = *(const uint32_t*)&As[ra0 + 8 + 2*t];
                uint32_t a3 = *(const uint32_t*)&As[ra1 + 8 + 2*t];
                #pragma unroll
                for (int j = 0; j < 8; j++) {
                    asm volatile(
                        "mma.sync.aligned.m16n8k16.row.col.f32.bf16.bf16.f32 "
                        "{%0,%1,%2,%3}, {%4,%5,%6,%7}, {%8,%9}, {%0,%1,%2,%3};"
                        : "+f"(acc[i][j][0]), "+f"(acc[i][j][1]),
                          "+f"(acc[i][j][2]), "+f"(acc[i][j][3])
                        : "r"(a0), "r"(a1), "r"(a2), "r"(a3),
                          "r"(bf[j][0]), "r"(bf[j][1]));
                }
            }
        }
        __syncthreads();
    }

    if (!FUSED) {
        #pragma unroll
        for (int i = 0; i < 2; i++) {
            int r0 = bm + wm + i*16 + g;
            int r1 = r0 + 8;
            #pragma unroll
            for (int j = 0; j < 8; j++) {
                int col = bn + wn + j*8 + 2*t;
                float b0 = bias ? bias[col]   : 0.f;
                float b1 = bias ? bias[col+1] : 0.f;
                if (r0 < M) *(float2*)(C + (size_t)r0 * ldc + col) =
                    make_float2(acc[i][j][0] + b0, acc[i][j][1] + b1);
                if (r1 < M) *(float2*)(C + (size_t)r1 * ldc + col) =
                    make_float2(acc[i][j][2] + b0, acc[i][j][3] + b1);
            }
        }
    } else {
        #pragma unroll
        for (int i = 0; i < 2; i++) {
            #pragma unroll
            for (int half = 0; half < 2; half++) {
                float mx = -1e30f;
                #pragma unroll
                for (int j = 0; j < 8; j++) {
                    mx = fmaxf(mx, acc[i][j][half*2+0]);
                    mx = fmaxf(mx, acc[i][j][half*2+1]);
                }
                float s = 0.f;
                #pragma unroll
                for (int j = 0; j < 8; j++) {
                    s += expf(acc[i][j][half*2+0] - mx);
                    s += expf(acc[i][j][half*2+1] - mx);
                }
                #pragma unroll
                for (int m = 1; m < 4; m <<= 1) {
                    float M2 = __shfl_xor_sync(0xffffffff, mx, m);
                    float S2 = __shfl_xor_sync(0xffffffff, s,  m);
                    float Mn = fmaxf(mx, M2);
                    s = s * expf(mx - Mn) + S2 * expf(M2 - Mn);
                    mx = Mn;
                }
                if (t == 0) {
                    int rloc = wm + i*16 + half*8 + g;
                    smx[wid & 1][rloc] = mx;
                    sms[wid & 1][rloc] = s;
                }
            }
        }
        __syncthreads();
        if (tid < 128) {
            int gm = bm + tid;
            if (gm < M) {
                float m0 = smx[0][tid], m1 = smx[1][tid];
                float Mn = fmaxf(m0, m1);
                float S  = sms[0][tid] * expf(m0 - Mn) + sms[1][tid] * expf(m1 - Mn);
                pmax[(size_t)blockIdx.x * 4096 + gm] = Mn;
                psum[(size_t)blockIdx.x * 4096 + gm] = S;
            }
        }
    }
}

// ================= bf16 recurrent GEMM (M=64, K-split) =================
// out_slice[s][b][bn+n] = sum_{k in split s} A[b*lda+k] * W[(bn+n)*ldw+k]
// tile 64x64, 128 threads = 4 warps (warp w: rows 16w..16w+15, all 64 cols).
// K-chunk 64; Kper % 64 == 0.
__global__ __launch_bounds__(128)
void rgemm(const float* __restrict__ A, int lda,
           const __nv_bfloat16* __restrict__ W, int ldw,
           float* __restrict__ out, int Ntot, int Kper, size_t slotStride) {
    __shared__ __align__(16) __nv_bfloat16 As[64 * SASTR];
    __shared__ __align__(16) __nv_bfloat16 Ws[64 * SASTR];
    const int bn = blockIdx.x * 64;
    const int s  = blockIdx.y;
    const int k0 = s * Kper;
    out += (size_t)s * slotStride;
    const int tid  = threadIdx.x;
    const int lane = tid & 31;
    const int wid  = tid >> 5;
    const int wm   = wid * 16;
    const int g    = lane >> 2;
    const int t    = lane & 3;

    float acc[8][4];
    #pragma unroll
    for (int j = 0; j < 8; j++)
        #pragma unroll
        for (int r = 0; r < 4; r++) acc[j][r] = 0.f;

    for (int kt = k0; kt < k0 + Kper; kt += 64) {
        // A: 64 rows x 64 k fp32.  1024 float4 / 128 thr = 8 each.
        #pragma unroll
        for (int q = 0; q < 8; q++) {
            int f = q * 128 + tid;
            int row = f >> 4;
            int c4 = (f & 15) << 2;
            float4 v = *(const float4*)(A + (size_t)row * lda + kt + c4);
            *(uint32_t*)&As[row * SASTR + c4]     = packbf(v.x, v.y);
            *(uint32_t*)&As[row * SASTR + c4 + 2] = packbf(v.z, v.w);
        }
        // W: 64 rows x 64 k bf16.  512 uint4 / 128 thr = 4 each.
        #pragma unroll
        for (int q = 0; q < 4; q++) {
            int f = q * 128 + tid;
            int row = f >> 3;
            int c8 = (f & 7) << 3;
            uint4 v = *(const uint4*)(W + (size_t)(bn + row) * ldw + kt + c8);
            *(uint4*)&Ws[row * SASTR + c8] = v;
        }
        __syncthreads();

        #pragma unroll
        for (int kk = 0; kk < 4; kk++) {
            int ra0 = (wm + g) * SASTR + kk*16;
            int ra1 = (wm + 8 + g) * SASTR + kk*16;
            uint32_t a0 = *(const uint32_t*)&As[ra0 + 2*t];
            uint32_t a1 = *(const uint32_t*)&As[ra1 + 2*t];
            uint32_t a2 = *(const uint32_t*)&As[ra0 + 8 + 2*t];
            uint32_t a3 = *(const uint32_t*)&As[ra1 + 8 + 2*t];
            #pragma unroll
            for (int j = 0; j < 8; j++) {
                int rb = (j*8 + g) * SASTR + kk*16;
                uint32_t b0 = *(const uint32_t*)&Ws[rb + 2*t];
                uint32_t b1 = *(const uint32_t*)&Ws[rb + 8 + 2*t];
                asm volatile(
                    "mma.sync.aligned.m16n8k16.row.col.f32.bf16.bf16.f32 "
                    "{%0,%1,%2,%3}, {%4,%5,%6,%7}, {%8,%9}, {%0,%1,%2,%3};"
                    : "+f"(acc[j][0]), "+f"(acc[j][1]),
                      "+f"(acc[j][2]), "+f"(acc[j][3])
                    : "r"(a0), "r"(a1), "r"(a2), "r"(a3),
                      "r"(b0), "r"(b1));
            }
        }
        __syncthreads();
    }
    int r0 = wm + g;
    int r1 = r0 + 8;
    #pragma unroll
    for (int j = 0; j < 8; j++) {
        int col = bn + j*8 + 2*t;
        *(float2*)(out + (size_t)r0 * Ntot + col) = make_float2(acc[j][0], acc[j][1]);
        *(float2*)(out + (size_t)r1 * Ntot + col) = make_float2(acc[j][2], acc[j][3]);
    }
}

// ---------------- fp32 small GEMM (one-off projections) ----------------
__global__ __launch_bounds__(256)
void pgemm(const float* __restrict__ A, int lda,
           const float* __restrict__ W, int ldw,
           float* __restrict__ out, int Ntot, int Kper, size_t slotStride) {
    __shared__ float As[16][68];
    __shared__ float Ws[16][68];
    const int bn = blockIdx.x * 64;
    const int s  = blockIdx.y;
    const int k0 = s * Kper;
    out += (size_t)s * slotStride;
    const int tid = threadIdx.x;
    const int lr = tid >> 2;
    const int lc = (tid & 3) << 2;
    const int ty = tid >> 4;
    const int tx = tid & 15;
    float acc[4][4];
    #pragma unroll
    for (int i = 0; i < 4; i++)
        #pragma unroll
        for (int j = 0; j < 4; j++) acc[i][j] = 0.f;

    for (int kt = k0; kt < k0 + Kper; kt += 16) {
        float4 v = *(const float4*)(A + (size_t)lr * lda + kt + lc);
        As[lc+0][lr] = v.x; As[lc+1][lr] = v.y; As[lc+2][lr] = v.z; As[lc+3][lr] = v.w;
        float4 w = *(const float4*)(W + (size_t)(bn + lr) * ldw + kt + lc);
        Ws[lc+0][lr] = w.x; Ws[lc+1][lr] = w.y; Ws[lc+2][lr] = w.z; Ws[lc+3][lr] = w.w;
        __syncthreads();
        #pragma unroll
        for (int k = 0; k < 16; k++) {
            float4 a = *(const float4*)&As[k][ty*4];
            float4 b = *(const float4*)&Ws[k][tx*4];
            float av[4] = {a.x,a.y,a.z,a.w};
            float bv[4] = {b.x,b.y,b.z,b.w};
            #pragma unroll
            for (int i = 0; i < 4; i++)
                #pragma unroll
                for (int j = 0; j < 4; j++) acc[i][j] += av[i] * bv[j];
        }
        __syncthreads();
    }
    #pragma unroll
    for (int i = 0; i < 4; i++) {
        int b = ty * 4 + i;
        #pragma unroll
        for (int j = 0; j < 4; j++)
            out[(size_t)b * Ntot + bn + tx * 4 + j] = acc[i][j];
    }
}

// ---------------- LSTM cell ----------------
__global__ void cell_k(const float* __restrict__ X, const float* __restrict__ part,
                       int ns, float* __restrict__ h, float* __restrict__ c,
                       float* __restrict__ outp, float* __restrict__ hcat,
                       const int* __restrict__ lens, int t) {
    int idx = blockIdx.x * 256 + threadIdx.x;
    int b = idx >> 10, j = idx & 1023;
    size_t base = (size_t)b * H4 + j;
    float gi = X[base], gf = X[base + HH], gg = X[base + 2*HH], go = X[base + 3*HH];
    for (int q = 0; q < ns; q++) {
        const float* p = part + (size_t)q * (BB*H4);
        gi += p[base]; gf += p[base + HH]; gg += p[base + 2*HH]; go += p[base + 3*HH];
    }
    float cold = c[idx];
    float c2 = sigm(gf) * cold + sigm(gi) * tanhf(gg);
    float h2 = sigm(go) * tanhf(c2);
    bool m = lens ? (t < lens[b]) : true;
    float hn = m ? h2 : h[idx];
    h[idx] = hn;
    c[idx] = m ? c2 : cold;
    if (outp) outp[idx] = m ? h2 : 0.f;
    if (hcat) hcat[(size_t)b * 2048 + j] = hn;
}

// ---------------- attention ----------------
__global__ __launch_bounds__(256)
void att_k(const float* __restrict__ encp, const float* __restrict__ ench,
           const float* __restrict__ h, const int* __restrict__ lens,
           float* __restrict__ cat) {
    __shared__ float e[64];
    __shared__ float alpha[64];
    const int b = blockIdx.x;
    const int tid = threadIdx.x;
    const int w = tid >> 5, l = tid & 31;
    const int len = lens[b];
    for (int t = w; t < 64; t += 8) {
        const float* ep = encp + ((size_t)b * 64 + t) * HH;
        const float* hp = h + (size_t)b * HH;
        float s = 0.f;
        for (int k = l; k < HH; k += 32) s += ep[k] * hp[k];
        #pragma unroll
        for (int m = 16; m > 0; m >>= 1) s += __shfl_xor_sync(0xffffffff, s, m);
        if (l == 0) e[t] = s;
    }
    __syncthreads();
    if (tid == 0) {
        float mx = -1e30f;
        for (int t = 0; t < len; t++) mx = fmaxf(mx, e[t]);
        float sm = 0.f;
        for (int t = 0; t < len; t++) sm += expf(e[t] - mx);
        float inv = 1.f / sm;
        for (int t = 0; t < 64; t++) alpha[t] = (t < len) ? expf(e[t] - mx) * inv : 0.f;
    }
    __syncthreads();
    const float* eh = ench + (size_t)b * (64 * 2048);
    for (int d = tid; d < 2048; d += 256) {
        float s = 0.f;
        for (int t = 0; t < len; t++) s += alpha[t] * eh[(size_t)t * 2048 + d];
        cat[(size_t)b * 3072 + d] = s;
    }
    for (int d = tid; d < 1024; d += 256)
        cat[(size_t)b * 3072 + 2048 + d] = h[(size_t)b * HH + d];
}

// ---------------- lse / gold / final ----------------
__global__ void lse_k(const float* __restrict__ pmax, const float* __restrict__ psum,
                      float* __restrict__ lse, int M) {
    int row = blockIdx.x * 4 + (threadIdx.x >> 5);
    int l = threadIdx.x & 31;
    if (row >= M) return;
    float Mx = -1e30f, S = 0.f;
    for (int c = l; c < 250; c += 32) {
        float m2 = pmax[(size_t)c * 4096 + row];
        float s2 = psum[(size_t)c * 4096 + row];
        float Mn = fmaxf(Mx, m2);
        S = S * expf(Mx - Mn) + s2 * expf(m2 - Mn);
        Mx = Mn;
    }
    #pragma unroll
    for (int m = 16; m > 0; m >>= 1) {
        float M2 = __shfl_xor_sync(0xffffffff, Mx, m);
        float S2 = __shfl_xor_sync(0xffffffff, S, m);
        float Mn = fmaxf(Mx, M2);
        S = S * expf(Mx - Mn) + S2 * expf(M2 - Mn);
        Mx = Mn;
    }
    if (l == 0) lse[row] = Mx + logf(S);
}

__global__ void gold_k(const float* __restrict__ outs, const __nv_bfloat16* __restrict__ Wv,
                       const int* __restrict__ tgt, float* __restrict__ gold, int M) {
    int row = blockIdx.x * 4 + (threadIdx.x >> 5);
    int l = threadIdx.x & 31;
    if (row >= M) return;
    int id = tgt[row + 64];
    const float* a = outs + (size_t)row * HH;
    const __nv_bfloat16* w = Wv + (size_t)id * HH;
    float s = 0.f;
    for (int k = l; k < HH; k += 32) {
        float av = __bfloat162float(__float2bfloat16(a[k]));
        s += av * __bfloat162float(w[k]);
    }
    #pragma unroll
    for (int m = 16; m > 0; m >>= 1) s += __shfl_xor_sync(0xffffffff, s, m);
    if (l == 0) gold[row] = s;
}

__global__ void final_k(const float* __restrict__ gold, const float* __restrict__ lse,
                        const int* __restrict__ tgt, float* __restrict__ out) {
    int b = threadIdx.x;
    if (b >= BB) return;
    float s = 0.f;
    for (int t = 0; t < TD; t++) {
        int r = t * BB + b;
        if (tgt[r + 64] != 0) s += gold[r] - lse[r];
    }
    out[b] = s;
}

// ---------------- host launch ----------------
extern "C" void kernel_launch(void* const* d_in, const int* in_sizes, int n_in,
                              void* d_out, int out_size) {
    const int*   src_pad = (const int*)  d_in[0];
    const int*   tgt_pad = (const int*)  d_in[1];
    const int*   lens    = (const int*)  d_in[2];
    const float* src_emb = (const float*)d_in[3];
    const float* dst_emb = (const float*)d_in[4];
    const float* Wihf = (const float*)d_in[5];
    const float* Whhf = (const float*)d_in[6];
    const float* bihf = (const float*)d_in[7];
    const float* bhhf = (const float*)d_in[8];
    const float* Wihb = (const float*)d_in[9];
    const float* Whhb = (const float*)d_in[10];
    const float* bihb = (const float*)d_in[11];
    const float* bhhb = (const float*)d_in[12];
    const float* Wihd = (const float*)d_in[13];
    const float* Whhd = (const float*)d_in[14];
    const float* bihd = (const float*)d_in[15];
    const float* bhhd = (const float*)d_in[16];
    const float* Whpr = (const float*)d_in[17];
    const float* Wcpr = (const float*)d_in[18];
    const float* Watt = (const float*)d_in[19];
    const float* Wcmb = (const float*)d_in[20];
    const float* Wvoc = (const float*)d_in[21];
    float* out = (float*)d_out;

    float* gb;
    cudaGetSymbolAddress((void**)&gb, g_buf);
    __nv_bfloat16* bb;
    cudaGetSymbolAddress((void**)&bb, g_bf);

    float* X    = gb + OFF_X;
    float* Y    = gb + OFF_Y;
    float* XF   = gb + OFF_XF;
    float* XB   = gb + OFF_XB;
    float* YW   = gb + OFF_YW;
    float* OUTF = gb + OFF_OUTF;
    float* OUTB = gb + OFF_OUTB;
    float* ENCH = gb + OFF_ENCH;
    float* ENCP = gb + OFF_ENCP;
    float* OUTS = gb + OFF_OUTS;
    float* Hb   = gb + OFF_H;
    float* Cb   = gb + OFF_C;
    float* H0   = gb + OFF_H0;
    float* C0   = gb + OFF_C0;
    float* HCAT = gb + OFF_HCAT;
    float* CCAT = gb + OFF_CCAT;
    float* ATT  = gb + OFF_ATT;
    float* ACAT = gb + OFF_ACAT;
    float* PART = gb + OFF_PART;
    float* BS   = gb + OFF_BS;
    float* GOLD = gb + OFF_GOLD;
    float* LSE  = gb + OFF_LSE;
    float* PMAX = gb + OFF_PMAX;
    float* PSUM = gb + OFF_PSUM;

    __nv_bfloat16* BWVOC = bb + BOFF_WVOC;
    __nv_bfloat16* BWHHF = bb + BOFF_WHHF;
    __nv_bfloat16* BWHHB = bb + BOFF_WHHB;
    __nv_bfloat16* BWCAT = bb + BOFF_WCAT;
    __nv_bfloat16* BWIHF = bb + BOFF_WIHF;
    __nv_bfloat16* BWIHB = bb + BOFF_WIHB;
    __nv_bfloat16* BWIHDY= bb + BOFF_WIHDY;
    __nv_bfloat16* BWATT = bb + BOFF_WATT;
    __nv_bfloat16* BWCMB = bb + BOFF_WCMB;

    const size_t SS4 = (size_t)BB * H4;
    const size_t SS1 = (size_t)BB * HH;

    // weight conversions (bf16)
    auto g4 = [](size_t n) { return (unsigned)((n/4 + 255) / 256); };
    cvt_rows<<<g4((size_t)VV*HH), 256>>>(BWVOC, Wvoc, VV, HH, HH);
    cvt_rows<<<g4((size_t)H4*HH), 256>>>(BWHHF, Whhf, H4, HH, HH);
    cvt_rows<<<g4((size_t)H4*HH), 256>>>(BWHHB, Whhb, H4, HH, HH);
    cvt_rows<<<g4((size_t)H4*EE), 256>>>(BWIHF, Wihf, H4, EE, EE);
    cvt_rows<<<g4((size_t)H4*EE), 256>>>(BWIHB, Wihb, H4, EE, EE);
    cvt_rows<<<g4((size_t)H4*EE), 256>>>(BWIHDY, Wihd, H4, EE, 3*EE);
    cvt_rows<<<g4((size_t)HH*2*HH), 256>>>(BWATT, Watt, HH, 2*HH, 2*HH);
    cvt_rows<<<g4((size_t)HH*3*HH), 256>>>(BWCMB, Wcmb, HH, 3*HH, 3*HH);
    cvt_cat<<<g4((size_t)H4*2048), 256>>>(BWCAT, Whhd, Wihd);

    bias3_k<<<16, 256>>>(BS, bihf, bhhf, bihb, bhhb, bihd, bhhd);
    gather_k<<<TSRC*BB, 128>>>(X, src_emb, src_pad);
    gather_k<<<TD*BB, 128>>>(Y, dst_emb, tgt_pad);

    // input GEMMs (bf16 MMA)
    bgemm<false><<<dim3(32, 32), 256>>>(X, EE, BWIHF, EE, XF, H4, TSRC*BB, EE, BS, nullptr, nullptr);
    bgemm<false><<<dim3(32, 32), 256>>>(X, EE, BWIHB, EE, XB, H4, TSRC*BB, EE, BS + H4, nullptr, nullptr);
    bgemm<false><<<dim3(32, 32), 256>>>(Y, EE, BWIHDY, EE, YW, H4, TD*BB, EE, BS + 2*H4, nullptr, nullptr);

    // forward encoder
    zero_k<<<512, 256>>>(Hb, 2 * BB * HH);
    for (int t = 0; t < TSRC; t++) {
        rgemm<<<dim3(64, 4), 128>>>(Hb, HH, BWHHF, HH, PART, H4, 256, SS4);
        cell_k<<<256, 256>>>(XF + (size_t)t * SS4, PART, 4, Hb, Cb,
                             OUTF + (size_t)t * SS1, nullptr, lens, t);
    }
    copycat_k<<<256, 256>>>(HCAT, Hb, 0);
    copycat_k<<<256, 256>>>(CCAT, Cb, 0);

    // backward encoder
    zero_k<<<512, 256>>>(Hb, 2 * BB * HH);
    for (int tt = 0; tt < TSRC; tt++) {
        int t = TSRC - 1 - tt;
        rgemm<<<dim3(64, 4), 128>>>(Hb, HH, BWHHB, HH, PART, H4, 256, SS4);
        cell_k<<<256, 256>>>(XB + (size_t)t * SS4, PART, 4, Hb, Cb,
                             OUTB + (size_t)t * SS1, nullptr, lens, t);
    }
    copycat_k<<<256, 256>>>(HCAT, Hb, HH);
    copycat_k<<<256, 256>>>(CCAT, Cb, HH);

    ench_k<<<16384, 256>>>(ENCH, OUTF, OUTB);

    // h0 / c0 projections (fp32, one-off)
    pgemm<<<dim3(16, 4), 256>>>(HCAT, 2*HH, Whpr, 2*HH, PART, HH, 512, SS1);
    sumsl_k<<<256, 256>>>(H0, PART, 4);
    pgemm<<<dim3(16, 4), 256>>>(CCAT, 2*HH, Wcpr, 2*HH, PART, HH, 512, SS1);
    sumsl_k<<<256, 256>>>(C0, PART, 4);

    // enc_proj
    bgemm<false><<<dim3(8, 32), 256>>>(ENCH, 2*HH, BWATT, 2*HH, ENCP, HH, TSRC*BB, 2*HH, nullptr, nullptr, nullptr);

    // decoder: ACAT = [h | o_prev]
    zero_k<<<512, 256>>>(ACAT, BB * 2 * HH);
    cat_h<<<256, 256>>>(ACAT, H0);
    for (int t = 0; t < TD; t++) {
        rgemm<<<dim3(64, 8), 128>>>(ACAT, 2*HH, BWCAT, 2*HH, PART, H4, 256, SS4);
        cell_k<<<256, 256>>>(YW + (size_t)t * SS4, PART, 8, H0, C0, nullptr, ACAT, nullptr, 0);
        att_k<<<64, 256>>>(ENCP, ENCH, H0, lens, ATT);
        rgemm<<<dim3(16, 8), 128>>>(ATT, 3*HH, BWCMB, 3*HH, PART, HH, 384, SS1);
        tanhsum_k<<<256, 256>>>(OUTS + (size_t)t * SS1, PART, 8, ACAT);
    }

    // vocab (bf16 MMA + fused chunk stats)
    bgemm<true><<<dim3(250, 32), 256>>>(OUTS, HH, BWVOC, HH, nullptr, 0, TD*BB, HH, nullptr, PMAX, PSUM);
    lse_k<<<1008, 128>>>(PMAX, PSUM, LSE, TD*BB);
    gold_k<<<1008, 128>>>(OUTS, BWVOC, tgt_pad, GOLD, TD*BB);
    final_k<<<1, 64>>>(GOLD, LSE, tgt_pad, out);
}